// round 11
// baseline (speedup 1.0000x reference)
#include <cuda_runtime.h>
#include <cuda_bf16.h>
#include <cstdint>

#define B_    4096
#define FIN   64
#define NK    512
#define FOUT  256
#define TB    32
#define NTHR  256
#define AP    40            // A pitch in b32: conflict-free fragment access
#define XRP   68            // staged x pitch (floats)

typedef unsigned long long ull;

__device__ float    g_cc[NK];
__device__ float    g_s2[NK];
__device__ uint32_t g_Wpk[131072];   // 512KB: phase-3 B fragments, register order
__device__ uint4    g_Cpk[8192];     // 128KB: phase-1 B fragments (centers split-bf16)

// ---- smem (u32 offsets) ----
#define SM_A    0               // [512 kp_eff][AP]: kp 0-255 = R_hi, 256-511 = R_lo
#define SM_XR   20480           // staged x [32][XRP] floats
#define SM_XF   22656           // x fragments: 16 frags x 32 lanes x uint4
#define SM_PART 24704           // [8][32]
#define SM_INV  24960
#define SM_XX   24992
#define SM_CC   25024
#define SM_S2   25536
#define SM_TOT  26048
#define SMEM_BYTES (SM_TOT * 4) // ~102 KB -> 2 CTAs/SM

__device__ __forceinline__ uint32_t pack_bf2(__nv_bfloat16 a, __nv_bfloat16 b) {
    __nv_bfloat162 t; t.x = a; t.y = b;
    return *reinterpret_cast<uint32_t*>(&t);
}
__device__ __forceinline__ uint32_t split_hi(float a, float b) {
    return pack_bf2(__float2bfloat16(a), __float2bfloat16(b));
}
__device__ __forceinline__ uint32_t split_lo(float a, float b) {
    __nv_bfloat16 ha = __float2bfloat16(a), hb = __float2bfloat16(b);
    return pack_bf2(__float2bfloat16(a - __bfloat162float(ha)),
                    __float2bfloat16(b - __bfloat162float(hb)));
}

#define MMA16816(D,a0,a1,a2,a3,b0,b1) \
    asm("mma.sync.aligned.m16n8k16.row.col.f32.bf16.bf16.f32 " \
        "{%0,%1,%2,%3}, {%4,%5,%6,%7}, {%8,%9}, {%0,%1,%2,%3};" \
        : "+f"(D[0]), "+f"(D[1]), "+f"(D[2]), "+f"(D[3]) \
        : "r"(a0), "r"(a1), "r"(a2), "r"(a3), "r"(b0), "r"(b1))

// -------- prep: stats, W pack (coalesced reads), centers pack --------
__global__ void prep_all(const float* __restrict__ W,
                         const float* __restrict__ centers,
                         const float* __restrict__ ls) {
    int bid = blockIdx.x;
    if (bid < 16) {
        int kb = bid * 32;
        int warp = threadIdx.x >> 5, lane = threadIdx.x & 31;
        #pragma unroll
        for (int c = warp; c < 32; c += 8) {
            int k = kb + c;
            float v0 = centers[k * FIN + lane];
            float v1 = centers[k * FIN + 32 + lane];
            float s = fmaf(v0, v0, v1 * v1);
            #pragma unroll
            for (int off = 16; off; off >>= 1) s += __shfl_xor_sync(0xffffffffu, s, off);
            if (lane == 0) g_cc[k] = s;
        }
        if (threadIdx.x < 32) g_s2[kb + threadIdx.x] = __expf(2.f * ls[kb + threadIdx.x]);
    } else if (bid < 528) {
        // W pack, coalesced reads: thread <- (split, col, kpair)
        int q = (bid - 16) * 256 + threadIdx.x;   // 0..131071
        int split = q >> 16;                      // 0 = hi, 1 = lo
        int rem   = q & 65535;
        int col   = rem >> 8;                     // 0..255
        int kp2   = rem & 255;                    // k-pair, consecutive per lane
        float2 wv = *(const float2*)(W + (size_t)col * NK + 2 * kp2);
        int h   = split * 8 + (kp2 >> 5);
        int kl  = kp2 & 31;
        int tig = kl & 3, ki = (kl >> 2) & 1, ks = kl >> 3;
        int g   = col & 7, t = (col >> 3) & 3, wn = col >> 5;
        int j   = 2 * t + ki, half = j >> 2, jp = j & 3;
        int lane = g * 4 + tig;
        int qo = jp | (lane << 2) | (half << 7) | (ks << 8) | (wn << 10) | (h << 13);
        g_Wpk[qo] = split ? split_lo(wv.x, wv.y) : split_hi(wv.x, wv.y);
    } else {
        // phase-1 centers pack (verified R9 layout)
        int q = (bid - 528) * 256 + threadIdx.x;   // 0..8191
        int lane = q & 31;
        int tp   = (q >> 5) & 1;
        int phys = (q >> 6) & 7;
        int w    = q >> 9;
        int g    = lane >> 2;
        int tig  = lane & 3;
        int ks   = phys & 3;
        bool lo  = phys >= 4;
        int colA = w * 32 + (2 * tp) * 8 + g;
        int colB = colA + 8;
        int k0   = 16 * ks + 2 * tig;
        int k1   = k0 + 8;
        const float* cA = centers + (size_t)colA * FIN;
        const float* cB = centers + (size_t)colB * FIN;
        float2 a0 = *(const float2*)(cA + k0);
        float2 a1 = *(const float2*)(cA + k1);
        float2 b0 = *(const float2*)(cB + k0);
        float2 b1 = *(const float2*)(cB + k1);
        uint4 r;
        if (lo) {
            r.x = split_lo(a0.x, a0.y); r.y = split_lo(a1.x, a1.y);
            r.z = split_lo(b0.x, b0.y); r.w = split_lo(b1.x, b1.y);
        } else {
            r.x = split_hi(a0.x, a0.y); r.y = split_hi(a1.x, a1.y);
            r.z = split_hi(b0.x, b0.y); r.w = split_hi(b1.x, b1.y);
        }
        g_Cpk[q] = r;
    }
}

// -------- fused main kernel: 256 thr, grid = 128 row-tiles x 2 col-halves --------
__global__ __launch_bounds__(NTHR, 2)
void rbf_main(const float* __restrict__ x,
              float* __restrict__ out) {
    extern __shared__ float sm[];
    uint32_t* A32 = (uint32_t*)sm;
    const int tid  = threadIdx.x;
    const int lane = tid & 31;
    const int warp = tid >> 5;          // 0..7
    const int g    = lane >> 2;
    const int tig  = lane & 3;
    const int b0   = (blockIdx.x >> 1) * TB;
    const int nh   = blockIdx.x & 1;    // output col half

    // ---- stage 1: coalesced x tile load + per-k constants ----
    sm[SM_CC + tid]       = g_cc[tid];
    sm[SM_CC + tid + 256] = g_cc[tid + 256];
    sm[SM_S2 + tid]       = g_s2[tid];
    sm[SM_S2 + tid + 256] = g_s2[tid + 256];
    {
        const float4* x4 = (const float4*)(x + (size_t)b0 * FIN);
        #pragma unroll
        for (int i = 0; i < 2; i++) {
            int q = tid + i * 256;
            int r = q >> 4, c = q & 15;
            *(float4*)&sm[SM_XR + r * XRP + c * 4] = __ldg(x4 + q);
        }
    }
    __syncthreads();

    // ---- stage 2a: ||x||^2 (warp w handles rows 4w..4w+3, 8 lanes each) ----
    {
        int row = 4 * warp + (lane >> 3);
        int cg  = (lane & 7) * 8;
        float4 v0 = *(const float4*)&sm[SM_XR + row * XRP + cg];
        float4 v1 = *(const float4*)&sm[SM_XR + row * XRP + cg + 4];
        float s = fmaf(v0.x, v0.x, v0.y * v0.y) + fmaf(v0.z, v0.z, v0.w * v0.w)
                + fmaf(v1.x, v1.x, v1.y * v1.y) + fmaf(v1.z, v1.z, v1.w * v1.w);
        s += __shfl_xor_sync(0xffffffffu, s, 1);
        s += __shfl_xor_sync(0xffffffffu, s, 2);
        s += __shfl_xor_sync(0xffffffffu, s, 4);
        if ((lane & 7) == 0) sm[SM_XX + row] = s;
    }
    // ---- stage 2b: build shared x fragments (2 per thread) ----
    #pragma unroll
    for (int i = 0; i < 2; i++) {
        int q   = tid + i * 256;
        int fid = q >> 5;
        int gg  = (q >> 2) & 7;
        int tt  = q & 3;
        int m   = fid >> 3, ks = (fid >> 1) & 3, sp = fid & 1;
        int row0 = gg + 16 * m;
        int col0 = 16 * ks + 2 * tt;
        float2 u0 = *(const float2*)&sm[SM_XR + row0 * XRP + col0];
        float2 u1 = *(const float2*)&sm[SM_XR + (row0 + 8) * XRP + col0];
        float2 u2 = *(const float2*)&sm[SM_XR + row0 * XRP + col0 + 8];
        float2 u3 = *(const float2*)&sm[SM_XR + (row0 + 8) * XRP + col0 + 8];
        uint4 fr;
        if (sp) {
            fr.x = split_lo(u0.x, u0.y); fr.y = split_lo(u1.x, u1.y);
            fr.z = split_lo(u2.x, u2.y); fr.w = split_lo(u3.x, u3.y);
        } else {
            fr.x = split_hi(u0.x, u0.y); fr.y = split_hi(u1.x, u1.y);
            fr.z = split_hi(u2.x, u2.y); fr.w = split_hi(u3.x, u3.y);
        }
        ((uint4*)((uint32_t*)sm + SM_XF))[q] = fr;
    }
    __syncthreads();

    // ---- phase 1: warp covers cols [64w, 64w+64) in two 32-col passes ----
    const uint4* XFv = (const uint4*)((uint32_t*)sm + SM_XF);
    float psumr[4] = {0.f, 0.f, 0.f, 0.f};

    #pragma unroll
    for (int p = 0; p < 2; p++) {
        const int wcol = 2 * warp + p;        // 32-col group 0..15
        float acc[2][4][4];
        #pragma unroll
        for (int m = 0; m < 2; m++)
            #pragma unroll
            for (int nt = 0; nt < 4; nt++)
                #pragma unroll
                for (int i = 0; i < 4; i++) acc[m][nt][i] = 0.f;

        const uint4* cp = g_Cpk + (size_t)wcol * 512;
        #pragma unroll
        for (int ks = 0; ks < 4; ks++) {
            uint4 bh0 = __ldg(cp + (ks * 2 + 0) * 32 + lane);
            uint4 bh1 = __ldg(cp + (ks * 2 + 1) * 32 + lane);
            uint4 bl0 = __ldg(cp + ((4 + ks) * 2 + 0) * 32 + lane);
            uint4 bl1 = __ldg(cp + ((4 + ks) * 2 + 1) * 32 + lane);
            #pragma unroll
            for (int m = 0; m < 2; m++) {
                uint4 ah = XFv[((m * 4 + ks) * 2 + 0) * 32 + lane];
                uint4 al = XFv[((m * 4 + ks) * 2 + 1) * 32 + lane];
                MMA16816(acc[m][0], ah.x, ah.y, ah.z, ah.w, bh0.x, bh0.y);
                MMA16816(acc[m][1], ah.x, ah.y, ah.z, ah.w, bh0.z, bh0.w);
                MMA16816(acc[m][2], ah.x, ah.y, ah.z, ah.w, bh1.x, bh1.y);
                MMA16816(acc[m][3], ah.x, ah.y, ah.z, ah.w, bh1.z, bh1.w);
                MMA16816(acc[m][0], ah.x, ah.y, ah.z, ah.w, bl0.x, bl0.y);
                MMA16816(acc[m][1], ah.x, ah.y, ah.z, ah.w, bl0.z, bl0.w);
                MMA16816(acc[m][2], ah.x, ah.y, ah.z, ah.w, bl1.x, bl1.y);
                MMA16816(acc[m][3], ah.x, ah.y, ah.z, ah.w, bl1.z, bl1.w);
                MMA16816(acc[m][0], al.x, al.y, al.z, al.w, bh0.x, bh0.y);
                MMA16816(acc[m][1], al.x, al.y, al.z, al.w, bh0.z, bh0.w);
                MMA16816(acc[m][2], al.x, al.y, al.z, al.w, bh1.x, bh1.y);
                MMA16816(acc[m][3], al.x, al.y, al.z, al.w, bh1.z, bh1.w);
            }
        }

        // epilogue for this 32-col group: r2 -> exp -> A-tile + psum
        #pragma unroll
        for (int m = 0; m < 2; m++) {
            const int row0 = g + 16 * m;
            const int row1 = row0 + 8;
            const float xx0 = sm[SM_XX + row0];
            const float xx1 = sm[SM_XX + row1];
            #pragma unroll
            for (int nt = 0; nt < 4; nt++) {
                const int colp = wcol * 32 + nt * 8 + 2 * tig;
                const int kp   = colp >> 1;
                const float cc0 = sm[SM_CC + colp], cc1 = sm[SM_CC + colp + 1];
                const float s20 = sm[SM_S2 + colp], s21 = sm[SM_S2 + colp + 1];
                float r2, v00, v01, v10, v11;
                r2 = fmaf(-2.f, acc[m][nt][0], xx0 + cc0); v00 = __expf(-s20 * r2);
                r2 = fmaf(-2.f, acc[m][nt][1], xx0 + cc1); v01 = __expf(-s21 * r2);
                r2 = fmaf(-2.f, acc[m][nt][2], xx1 + cc0); v10 = __expf(-s20 * r2);
                r2 = fmaf(-2.f, acc[m][nt][3], xx1 + cc1); v11 = __expf(-s21 * r2);
                psumr[m * 2 + 0] += v00 + v01;
                psumr[m * 2 + 1] += v10 + v11;
                A32[(kp      ) * AP + row0] = split_hi(v00, v01);
                A32[(kp      ) * AP + row1] = split_hi(v10, v11);
                A32[(kp + 256) * AP + row0] = split_lo(v00, v01);
                A32[(kp + 256) * AP + row1] = split_lo(v10, v11);
            }
        }
    }
    #pragma unroll
    for (int i = 0; i < 4; i++) {
        psumr[i] += __shfl_xor_sync(0xffffffffu, psumr[i], 1);
        psumr[i] += __shfl_xor_sync(0xffffffffu, psumr[i], 2);
    }
    if (tig == 0) {
        sm[SM_PART + warp * 32 + g     ] = psumr[0];
        sm[SM_PART + warp * 32 + g + 8 ] = psumr[1];
        sm[SM_PART + warp * 32 + g + 16] = psumr[2];
        sm[SM_PART + warp * 32 + g + 24] = psumr[3];
    }
    __syncthreads();

    if (tid < 32) {
        float t = 1e-9f;
        #pragma unroll
        for (int w = 0; w < 8; w++) t += sm[SM_PART + w * 32 + tid];
        sm[SM_INV + tid] = 1.f / t;
    }
    __syncthreads();

    // ---- phase 3: this CTA covers cols [128*nh, 128*nh+128) ----
    const int wn  = nh * 4 + (warp & 3);    // global 32-col group 0..7
    const int wm  = warp >> 2;
    const int rofs = wm * 16;

    float pacc[4][4];
    #pragma unroll
    for (int t = 0; t < 4; t++)
        #pragma unroll
        for (int i = 0; i < 4; i++) pacc[t][i] = 0.f;

    const uint4* bsrc = (const uint4*)g_Wpk;
    const uint32_t* Ab = A32 + g + rofs;
    uint4 bA[4], bB[4];
    #pragma unroll
    for (int i = 0; i < 4; i++) {
        int ix = ((0 * 8 + wn) * 4 + (i & 3)) * 64 + lane;
        bA[i] = __ldg(bsrc + ix);
        bB[i] = __ldg(bsrc + ix + 32);
    }

    // loop 1: chunks 0-7 (W_hi) - R_hi and R_lo
    #pragma unroll 4
    for (int i = 0; i < 32; i++) {
        const int s  = i & 3;
        const int ks = i & 3;
        const int hk = i >> 2;
        const int kpA = hk * 32 + ks * 8 + tig;
        uint4 ba = bA[s], bb = bB[s];
        {
            const int nhk = (i + 4) >> 2, nks = (i + 4) & 3;
            const int ix = ((nhk * 8 + wn) * 4 + nks) * 64 + lane;
            bA[s] = __ldg(bsrc + ix);
            bB[s] = __ldg(bsrc + ix + 32);
        }
        uint32_t h0 = Ab[(kpA    ) * AP];
        uint32_t h1 = Ab[(kpA    ) * AP + 8];
        uint32_t h2 = Ab[(kpA + 4) * AP];
        uint32_t h3 = Ab[(kpA + 4) * AP + 8];
        MMA16816(pacc[0], h0, h1, h2, h3, ba.x, ba.y);
        MMA16816(pacc[1], h0, h1, h2, h3, ba.z, ba.w);
        MMA16816(pacc[2], h0, h1, h2, h3, bb.x, bb.y);
        MMA16816(pacc[3], h0, h1, h2, h3, bb.z, bb.w);
        uint32_t l0 = Ab[(kpA + 256) * AP];
        uint32_t l1 = Ab[(kpA + 256) * AP + 8];
        uint32_t l2 = Ab[(kpA + 260) * AP];
        uint32_t l3 = Ab[(kpA + 260) * AP + 8];
        MMA16816(pacc[0], l0, l1, l2, l3, ba.x, ba.y);
        MMA16816(pacc[1], l0, l1, l2, l3, ba.z, ba.w);
        MMA16816(pacc[2], l0, l1, l2, l3, bb.x, bb.y);
        MMA16816(pacc[3], l0, l1, l2, l3, bb.z, bb.w);
    }
    // loop 2: chunks 8-15 (W_lo) - R_hi only
    #pragma unroll 4
    for (int i = 32; i < 64; i++) {
        const int s  = i & 3;
        const int ks = i & 3;
        const int hk = (i >> 2) & 7;
        const int kpA = hk * 32 + ks * 8 + tig;
        uint4 ba = bA[s], bb = bB[s];
        if (i + 4 < 64) {
            const int nhk = (i + 4) >> 2, nks = (i + 4) & 3;
            const int ix = ((nhk * 8 + wn) * 4 + nks) * 64 + lane;
            bA[s] = __ldg(bsrc + ix);
            bB[s] = __ldg(bsrc + ix + 32);
        }
        uint32_t h0 = Ab[(kpA    ) * AP];
        uint32_t h1 = Ab[(kpA    ) * AP + 8];
        uint32_t h2 = Ab[(kpA + 4) * AP];
        uint32_t h3 = Ab[(kpA + 4) * AP + 8];
        MMA16816(pacc[0], h0, h1, h2, h3, ba.x, ba.y);
        MMA16816(pacc[1], h0, h1, h2, h3, ba.z, ba.w);
        MMA16816(pacc[2], h0, h1, h2, h3, bb.x, bb.y);
        MMA16816(pacc[3], h0, h1, h2, h3, bb.z, bb.w);
    }

    // ---- epilogue: normalize + store ----
    const int r0 = rofs + g, r1 = r0 + 8;
    const float i0 = sm[SM_INV + r0];
    const float i1 = sm[SM_INV + r1];
    #pragma unroll
    for (int t = 0; t < 4; t++) {
        const int col = wn * 32 + t * 8 + tig * 2;
        *(float2*)(out + (size_t)(b0 + r0) * FOUT + col) =
            make_float2(pacc[t][0] * i0, pacc[t][1] * i0);
        *(float2*)(out + (size_t)(b0 + r1) * FOUT + col) =
            make_float2(pacc[t][2] * i1, pacc[t][3] * i1);
    }
}

// -------- launch --------
extern "C" void kernel_launch(void* const* d_in, const int* in_sizes, int n_in,
                              void* d_out, int out_size) {
    const float* x       = (const float*)d_in[0];  // [4096, 64]
    const float* W       = (const float*)d_in[1];  // [256, 512]
    const float* centers = (const float*)d_in[2];  // [512, 64]
    const float* ls      = (const float*)d_in[3];  // [512]
    float* out = (float*)d_out;                    // [4096, 256]

    cudaFuncSetAttribute(rbf_main, cudaFuncAttributeMaxDynamicSharedMemorySize, SMEM_BYTES);

    prep_all<<<16 + 512 + 32, 256>>>(W, centers, ls);
    rbf_main<<<(B_ / TB) * 2, NTHR, SMEM_BYTES>>>(x, out);
}

// round 12
// speedup vs baseline: 1.2626x; 1.2626x over previous
#include <cuda_runtime.h>
#include <cuda_bf16.h>
#include <cstdint>

#define B_    4096
#define FIN   64
#define NK    512
#define FOUT  256
#define TB    32
#define NTHR  512
#define AP    40            // A pitch in b32: conflict-free fragment access
#define XRP   68            // staged x pitch (floats)

typedef unsigned long long ull;

__device__ float    g_cc[NK];
__device__ float    g_s2[NK];
__device__ uint32_t g_Wpk[131072];   // 512KB: phase-3 B fragments, register order
__device__ uint4    g_Cpk[8192];     // 128KB: phase-1 B fragments (centers split-bf16)

// ---- smem (u32 offsets) ----
#define SM_A    0               // [512 kp_eff][AP]: kp 0-255 = R_hi, 256-511 = R_lo
#define SM_XR   20480           // staged x [32][XRP] floats
#define SM_XF   22656           // x fragments: 16 frags x 32 lanes x uint4
#define SM_PART 24704           // [16][32]
#define SM_INV  25216
#define SM_XX   25248
#define SM_CC   25280
#define SM_S2   25792
#define SM_TOT  26304
#define SMEM_BYTES (SM_TOT * 4) // ~105 KB

__device__ __forceinline__ uint32_t pack_bf2(__nv_bfloat16 a, __nv_bfloat16 b) {
    __nv_bfloat162 t; t.x = a; t.y = b;
    return *reinterpret_cast<uint32_t*>(&t);
}
__device__ __forceinline__ uint32_t split_hi(float a, float b) {
    return pack_bf2(__float2bfloat16(a), __float2bfloat16(b));
}
__device__ __forceinline__ uint32_t split_lo(float a, float b) {
    __nv_bfloat16 ha = __float2bfloat16(a), hb = __float2bfloat16(b);
    return pack_bf2(__float2bfloat16(a - __bfloat162float(ha)),
                    __float2bfloat16(b - __bfloat162float(hb)));
}

#define MMA16816(D,a0,a1,a2,a3,b0,b1) \
    asm("mma.sync.aligned.m16n8k16.row.col.f32.bf16.bf16.f32 " \
        "{%0,%1,%2,%3}, {%4,%5,%6,%7}, {%8,%9}, {%0,%1,%2,%3};" \
        : "+f"(D[0]), "+f"(D[1]), "+f"(D[2]), "+f"(D[3]) \
        : "r"(a0), "r"(a1), "r"(a2), "r"(a3), "r"(b0), "r"(b1))

// -------- prep: stats, W pack (coalesced reads), centers pack --------
__global__ void prep_all(const float* __restrict__ W,
                         const float* __restrict__ centers,
                         const float* __restrict__ ls) {
    int bid = blockIdx.x;
    if (bid < 16) {
        int kb = bid * 32;
        int warp = threadIdx.x >> 5, lane = threadIdx.x & 31;
        #pragma unroll
        for (int c = warp; c < 32; c += 8) {
            int k = kb + c;
            float v0 = centers[k * FIN + lane];
            float v1 = centers[k * FIN + 32 + lane];
            float s = fmaf(v0, v0, v1 * v1);
            #pragma unroll
            for (int off = 16; off; off >>= 1) s += __shfl_xor_sync(0xffffffffu, s, off);
            if (lane == 0) g_cc[k] = s;
        }
        if (threadIdx.x < 32) g_s2[kb + threadIdx.x] = __expf(2.f * ls[kb + threadIdx.x]);
    } else if (bid < 528) {
        // W pack, coalesced reads: thread <- (split, col, kpair)
        int q = (bid - 16) * 256 + threadIdx.x;   // 0..131071
        int split = q >> 16;                      // 0 = hi, 1 = lo
        int rem   = q & 65535;
        int col   = rem >> 8;                     // 0..255
        int kp2   = rem & 255;                    // k-pair, consecutive per lane
        float2 wv = *(const float2*)(W + (size_t)col * NK + 2 * kp2);
        int h   = split * 8 + (kp2 >> 5);
        int kl  = kp2 & 31;
        int tig = kl & 3, ki = (kl >> 2) & 1, ks = kl >> 3;
        int g   = col & 7, t = (col >> 3) & 3, wn = col >> 5;
        int j   = 2 * t + ki, half = j >> 2, jp = j & 3;
        int lane = g * 4 + tig;
        int qo = jp | (lane << 2) | (half << 7) | (ks << 8) | (wn << 10) | (h << 13);
        g_Wpk[qo] = split ? split_lo(wv.x, wv.y) : split_hi(wv.x, wv.y);
    } else {
        // phase-1 centers pack (verified R9 layout)
        int q = (bid - 528) * 256 + threadIdx.x;   // 0..8191
        int lane = q & 31;
        int tp   = (q >> 5) & 1;
        int phys = (q >> 6) & 7;
        int w    = q >> 9;
        int g    = lane >> 2;
        int tig  = lane & 3;
        int ks   = phys & 3;
        bool lo  = phys >= 4;
        int colA = w * 32 + (2 * tp) * 8 + g;
        int colB = colA + 8;
        int k0   = 16 * ks + 2 * tig;
        int k1   = k0 + 8;
        const float* cA = centers + (size_t)colA * FIN;
        const float* cB = centers + (size_t)colB * FIN;
        float2 a0 = *(const float2*)(cA + k0);
        float2 a1 = *(const float2*)(cA + k1);
        float2 b0 = *(const float2*)(cB + k0);
        float2 b1 = *(const float2*)(cB + k1);
        uint4 r;
        if (lo) {
            r.x = split_lo(a0.x, a0.y); r.y = split_lo(a1.x, a1.y);
            r.z = split_lo(b0.x, b0.y); r.w = split_lo(b1.x, b1.y);
        } else {
            r.x = split_hi(a0.x, a0.y); r.y = split_hi(a1.x, a1.y);
            r.z = split_hi(b0.x, b0.y); r.w = split_hi(b1.x, b1.y);
        }
        g_Cpk[q] = r;
    }
}

// -------- fused main kernel: 512 thr, grid 128, 1 CTA/SM --------
__global__ __launch_bounds__(NTHR, 1)
void rbf_main(const float* __restrict__ x,
              float* __restrict__ out) {
    extern __shared__ float sm[];
    uint32_t* A32 = (uint32_t*)sm;
    const int tid  = threadIdx.x;
    const int lane = tid & 31;
    const int warp = tid >> 5;
    const int g    = lane >> 2;
    const int tig  = lane & 3;
    const int b0   = blockIdx.x * TB;

    // ---- stage 1: coalesced x tile load + per-k constants ----
    sm[SM_CC + tid] = g_cc[tid];
    sm[SM_S2 + tid] = g_s2[tid];
    {
        const float4* x4 = (const float4*)(x + (size_t)b0 * FIN);
        int r = tid >> 4, c = tid & 15;
        *(float4*)&sm[SM_XR + r * XRP + c * 4] = __ldg(x4 + tid);
    }
    __syncthreads();

    // ---- stage 2a: ||x||^2 (warp w handles rows 2w, 2w+1) ----
    {
        int row = 2 * warp + (lane >> 4);
        float4 v = *(const float4*)&sm[SM_XR + row * XRP + (lane & 15) * 4];
        float s = fmaf(v.x, v.x, v.y * v.y) + fmaf(v.z, v.z, v.w * v.w);
        s += __shfl_xor_sync(0xffffffffu, s, 1);
        s += __shfl_xor_sync(0xffffffffu, s, 2);
        s += __shfl_xor_sync(0xffffffffu, s, 4);
        s += __shfl_xor_sync(0xffffffffu, s, 8);
        if ((lane & 15) == 0) sm[SM_XX + row] = s;
    }
    // ---- stage 2b: build shared x fragments (tid -> one uint4) ----
    {
        int fid = tid >> 5;
        int gg  = (tid >> 2) & 7;
        int tt  = tid & 3;
        int m   = fid >> 3, ks = (fid >> 1) & 3, sp = fid & 1;
        int row0 = gg + 16 * m;
        int col0 = 16 * ks + 2 * tt;
        float2 u0 = *(const float2*)&sm[SM_XR + row0 * XRP + col0];
        float2 u1 = *(const float2*)&sm[SM_XR + (row0 + 8) * XRP + col0];
        float2 u2 = *(const float2*)&sm[SM_XR + row0 * XRP + col0 + 8];
        float2 u3 = *(const float2*)&sm[SM_XR + (row0 + 8) * XRP + col0 + 8];
        uint4 fr;
        if (sp) {
            fr.x = split_lo(u0.x, u0.y); fr.y = split_lo(u1.x, u1.y);
            fr.z = split_lo(u2.x, u2.y); fr.w = split_lo(u3.x, u3.y);
        } else {
            fr.x = split_hi(u0.x, u0.y); fr.y = split_hi(u1.x, u1.y);
            fr.z = split_hi(u2.x, u2.y); fr.w = split_hi(u3.x, u3.y);
        }
        ((uint4*)((uint32_t*)sm + SM_XF))[tid] = fr;
    }
    __syncthreads();

    // ---- phase 1: tensor GEMM dot = x @ C^T; D = xh*(ch+cl) + xl*ch ----
    float acc[2][4][4];
    #pragma unroll
    for (int m = 0; m < 2; m++)
        #pragma unroll
        for (int nt = 0; nt < 4; nt++)
            #pragma unroll
            for (int i = 0; i < 4; i++) acc[m][nt][i] = 0.f;

    const uint4* cp  = g_Cpk + (size_t)warp * 512;
    const uint4* XFv = (const uint4*)((uint32_t*)sm + SM_XF);
    #pragma unroll
    for (int ks = 0; ks < 4; ks++) {
        uint4 bh0 = __ldg(cp + (ks * 2 + 0) * 32 + lane);
        uint4 bh1 = __ldg(cp + (ks * 2 + 1) * 32 + lane);
        uint4 bl0 = __ldg(cp + ((4 + ks) * 2 + 0) * 32 + lane);
        uint4 bl1 = __ldg(cp + ((4 + ks) * 2 + 1) * 32 + lane);
        #pragma unroll
        for (int m = 0; m < 2; m++) {
            uint4 ah = XFv[((m * 4 + ks) * 2 + 0) * 32 + lane];
            uint4 al = XFv[((m * 4 + ks) * 2 + 1) * 32 + lane];
            MMA16816(acc[m][0], ah.x, ah.y, ah.z, ah.w, bh0.x, bh0.y);
            MMA16816(acc[m][1], ah.x, ah.y, ah.z, ah.w, bh0.z, bh0.w);
            MMA16816(acc[m][2], ah.x, ah.y, ah.z, ah.w, bh1.x, bh1.y);
            MMA16816(acc[m][3], ah.x, ah.y, ah.z, ah.w, bh1.z, bh1.w);
            MMA16816(acc[m][0], ah.x, ah.y, ah.z, ah.w, bl0.x, bl0.y);
            MMA16816(acc[m][1], ah.x, ah.y, ah.z, ah.w, bl0.z, bl0.w);
            MMA16816(acc[m][2], ah.x, ah.y, ah.z, ah.w, bl1.x, bl1.y);
            MMA16816(acc[m][3], ah.x, ah.y, ah.z, ah.w, bl1.z, bl1.w);
            MMA16816(acc[m][0], al.x, al.y, al.z, al.w, bh0.x, bh0.y);
            MMA16816(acc[m][1], al.x, al.y, al.z, al.w, bh0.z, bh0.w);
            MMA16816(acc[m][2], al.x, al.y, al.z, al.w, bh1.x, bh1.y);
            MMA16816(acc[m][3], al.x, al.y, al.z, al.w, bh1.z, bh1.w);
        }
    }

    // ---- phase-1 epilogue: r2 -> exp -> split-bf16 A-tile + row partial sums ----
    float psumr[4] = {0.f, 0.f, 0.f, 0.f};
    #pragma unroll
    for (int m = 0; m < 2; m++) {
        const int row0 = g + 16 * m;
        const int row1 = row0 + 8;
        const float xx0 = sm[SM_XX + row0];
        const float xx1 = sm[SM_XX + row1];
        #pragma unroll
        for (int nt = 0; nt < 4; nt++) {
            const int colp = warp * 32 + nt * 8 + 2 * tig;
            const int kp   = colp >> 1;
            const float cc0 = sm[SM_CC + colp], cc1 = sm[SM_CC + colp + 1];
            const float s20 = sm[SM_S2 + colp], s21 = sm[SM_S2 + colp + 1];
            float r2, v00, v01, v10, v11;
            r2 = fmaf(-2.f, acc[m][nt][0], xx0 + cc0); v00 = __expf(-s20 * r2);
            r2 = fmaf(-2.f, acc[m][nt][1], xx0 + cc1); v01 = __expf(-s21 * r2);
            r2 = fmaf(-2.f, acc[m][nt][2], xx1 + cc0); v10 = __expf(-s20 * r2);
            r2 = fmaf(-2.f, acc[m][nt][3], xx1 + cc1); v11 = __expf(-s21 * r2);
            psumr[m * 2 + 0] += v00 + v01;
            psumr[m * 2 + 1] += v10 + v11;
            A32[(kp      ) * AP + row0] = split_hi(v00, v01);
            A32[(kp      ) * AP + row1] = split_hi(v10, v11);
            A32[(kp + 256) * AP + row0] = split_lo(v00, v01);
            A32[(kp + 256) * AP + row1] = split_lo(v10, v11);
        }
    }
    #pragma unroll
    for (int i = 0; i < 4; i++) {
        psumr[i] += __shfl_xor_sync(0xffffffffu, psumr[i], 1);
        psumr[i] += __shfl_xor_sync(0xffffffffu, psumr[i], 2);
    }
    if (tig == 0) {
        sm[SM_PART + warp * 32 + g     ] = psumr[0];
        sm[SM_PART + warp * 32 + g + 8 ] = psumr[1];
        sm[SM_PART + warp * 32 + g + 16] = psumr[2];
        sm[SM_PART + warp * 32 + g + 24] = psumr[3];
    }
    __syncthreads();

    if (tid < 32) {
        float t = 1e-9f;
        #pragma unroll
        for (int w = 0; w < 16; w++) t += sm[SM_PART + w * 32 + tid];
        sm[SM_INV + tid] = 1.f / t;
    }
    __syncthreads();

    // ---- phase 3: M2xN8 warps; nested loops (compact I$, strength-reduced) ----
    const int wn  = warp & 7;
    const int wm  = warp >> 3;
    const int rofs = wm * 16;

    float pacc[4][4];
    #pragma unroll
    for (int t = 0; t < 4; t++)
        #pragma unroll
        for (int i = 0; i < 4; i++) pacc[t][i] = 0.f;

    const uint4* bsrc = (const uint4*)g_Wpk;
    const uint32_t* Ab = A32 + g + rofs;
    int base = wn * 256 + lane;            // uint4 index of chunk 0, ks 0
    uint4 bA[4], bB[4];
    #pragma unroll
    for (int ks = 0; ks < 4; ks++) {
        bA[ks] = __ldg(bsrc + base + ks * 64);
        bB[ks] = __ldg(bsrc + base + ks * 64 + 32);
    }

    // loop 1: chunks 0-7 (W_hi) — R_hi and R_lo
    for (int c = 0; c < 8; c++) {
        const uint32_t* Ak = Ab + c * 32 * AP;
        #pragma unroll
        for (int ks = 0; ks < 4; ks++) {
            uint4 ba = bA[ks], bb = bB[ks];
            const int nix = base + 2048 + ks * 64;     // next chunk, same ks
            bA[ks] = __ldg(bsrc + nix);
            bB[ks] = __ldg(bsrc + nix + 32);
            const int kro = (ks * 8 + tig) * AP;
            uint32_t h0 = Ak[kro];
            uint32_t h1 = Ak[kro + 8];
            uint32_t h2 = Ak[kro + 4 * AP];
            uint32_t h3 = Ak[kro + 4 * AP + 8];
            MMA16816(pacc[0], h0, h1, h2, h3, ba.x, ba.y);
            MMA16816(pacc[1], h0, h1, h2, h3, ba.z, ba.w);
            MMA16816(pacc[2], h0, h1, h2, h3, bb.x, bb.y);
            MMA16816(pacc[3], h0, h1, h2, h3, bb.z, bb.w);
            uint32_t l0 = Ak[kro + 256 * AP];
            uint32_t l1 = Ak[kro + 256 * AP + 8];
            uint32_t l2 = Ak[kro + 260 * AP];
            uint32_t l3 = Ak[kro + 260 * AP + 8];
            MMA16816(pacc[0], l0, l1, l2, l3, ba.x, ba.y);
            MMA16816(pacc[1], l0, l1, l2, l3, ba.z, ba.w);
            MMA16816(pacc[2], l0, l1, l2, l3, bb.x, bb.y);
            MMA16816(pacc[3], l0, l1, l2, l3, bb.z, bb.w);
        }
        base += 2048;
    }
    // loop 2: chunks 8-15 (W_lo) — R_hi only
    for (int c = 0; c < 8; c++) {
        const uint32_t* Ak = Ab + c * 32 * AP;
        #pragma unroll
        for (int ks = 0; ks < 4; ks++) {
            uint4 ba = bA[ks], bb = bB[ks];
            if (c < 7) {
                const int nix = base + 2048 + ks * 64;
                bA[ks] = __ldg(bsrc + nix);
                bB[ks] = __ldg(bsrc + nix + 32);
            }
            const int kro = (ks * 8 + tig) * AP;
            uint32_t h0 = Ak[kro];
            uint32_t h1 = Ak[kro + 8];
            uint32_t h2 = Ak[kro + 4 * AP];
            uint32_t h3 = Ak[kro + 4 * AP + 8];
            MMA16816(pacc[0], h0, h1, h2, h3, ba.x, ba.y);
            MMA16816(pacc[1], h0, h1, h2, h3, ba.z, ba.w);
            MMA16816(pacc[2], h0, h1, h2, h3, bb.x, bb.y);
            MMA16816(pacc[3], h0, h1, h2, h3, bb.z, bb.w);
        }
        base += 2048;
    }

    // ---- epilogue: normalize + store ----
    const int r0 = rofs + g, r1 = r0 + 8;
    const float i0 = sm[SM_INV + r0];
    const float i1 = sm[SM_INV + r1];
    #pragma unroll
    for (int t = 0; t < 4; t++) {
        const int col = wn * 32 + t * 8 + tig * 2;
        *(float2*)(out + (size_t)(b0 + r0) * FOUT + col) =
            make_float2(pacc[t][0] * i0, pacc[t][1] * i0);
        *(float2*)(out + (size_t)(b0 + r1) * FOUT + col) =
            make_float2(pacc[t][2] * i1, pacc[t][3] * i1);
    }
}

// -------- launch --------
extern "C" void kernel_launch(void* const* d_in, const int* in_sizes, int n_in,
                              void* d_out, int out_size) {
    const float* x       = (const float*)d_in[0];  // [4096, 64]
    const float* W       = (const float*)d_in[1];  // [256, 512]
    const float* centers = (const float*)d_in[2];  // [512, 64]
    const float* ls      = (const float*)d_in[3];  // [512]
    float* out = (float*)d_out;                    // [4096, 256]

    cudaFuncSetAttribute(rbf_main, cudaFuncAttributeMaxDynamicSharedMemorySize, SMEM_BYTES);

    prep_all<<<16 + 512 + 32, 256>>>(W, centers, ls);
    rbf_main<<<B_ / TB, NTHR, SMEM_BYTES>>>(x, out);
}